// round 4
// baseline (speedup 1.0000x reference)
#include <cuda_runtime.h>
#include <cuda_bf16.h>
#include <cstdint>

#define N_NODES 50000
#define N_EDGES 1600000
#define CDIM 128
#define N_LAYERS 8

// ---------------- scratch (device globals; no allocation allowed) ----------
__device__ float g_h [N_NODES * CDIM];
__device__ float g_hw[N_NODES * CDIM];
__device__ float g_A [N_NODES * CDIM];
__device__ float g_B [N_NODES * CDIM];
__device__ float g_dis[N_NODES];
__device__ int   g_deg[N_NODES];
__device__ int   g_indptr[N_NODES + 1];
__device__ int   g_cursor[N_NODES];
__device__ int   g_csr_src[N_EDGES];
__device__ float g_csr_nrm[N_EDGES];
// transposed + hi/lo-split weights for node GEMMs: [10][n=128][k=128]
__device__ __nv_bfloat16 g_Wth[10 * 128 * 128];
__device__ __nv_bfloat16 g_Wtl[10 * 128 * 128];

// ---------------- helpers ----------------------------------------------------
__device__ __forceinline__ uint32_t f2tf32(float f) {
    uint32_t r;
    asm("cvt.rna.tf32.f32 %0, %1;" : "=r"(r) : "f"(f));
    return r;
}
__device__ __forceinline__ void mma_tf32(float d[4], const uint32_t a[4],
                                         uint32_t b0, uint32_t b1) {
    asm volatile(
        "mma.sync.aligned.m16n8k8.row.col.f32.tf32.tf32.f32 "
        "{%0,%1,%2,%3}, {%4,%5,%6,%7}, {%8,%9}, {%0,%1,%2,%3};"
        : "+f"(d[0]), "+f"(d[1]), "+f"(d[2]), "+f"(d[3])
        : "r"(a[0]), "r"(a[1]), "r"(a[2]), "r"(a[3]), "r"(b0), "r"(b1));
}
__device__ __forceinline__ void mma_bf16(float d[4], const uint32_t a[4],
                                         uint32_t b0, uint32_t b1) {
    asm volatile(
        "mma.sync.aligned.m16n8k16.row.col.f32.bf16.bf16.f32 "
        "{%0,%1,%2,%3}, {%4,%5,%6,%7}, {%8,%9}, {%0,%1,%2,%3};"
        : "+f"(d[0]), "+f"(d[1]), "+f"(d[2]), "+f"(d[3])
        : "r"(a[0]), "r"(a[1]), "r"(a[2]), "r"(a[3]), "r"(b0), "r"(b1));
}
__device__ __forceinline__ void ldmx4(uint32_t r[4], uint32_t addr) {
    asm volatile("ldmatrix.sync.aligned.m8n8.x4.shared.b16 {%0,%1,%2,%3}, [%4];"
                 : "=r"(r[0]), "=r"(r[1]), "=r"(r[2]), "=r"(r[3]) : "r"(addr));
}
__device__ __forceinline__ float4 f4add(float4 a, float4 b) {
    return make_float4(a.x + b.x, a.y + b.y, a.z + b.z, a.w + b.w);
}
__device__ __forceinline__ float4 f4relu(float4 a) {
    return make_float4(fmaxf(a.x, 0.f), fmaxf(a.y, 0.f), fmaxf(a.z, 0.f), fmaxf(a.w, 0.f));
}
__device__ __forceinline__ uint32_t pack_bf16(float a, float b) {
    uint32_t lo = (uint32_t)__bfloat16_as_ushort(__float2bfloat16(a));
    uint32_t hi = (uint32_t)__bfloat16_as_ushort(__float2bfloat16(b));
    return lo | (hi << 16);
}

// ---------------- setup kernels ---------------------------------------------
__global__ void k_zero_deg() {
    int i = blockIdx.x * blockDim.x + threadIdx.x;
    if (i < N_NODES) g_deg[i] = 0;
}

__global__ void k_count_deg(const int* __restrict__ col) {
    int e = blockIdx.x * blockDim.x + threadIdx.x;
    if (e < N_EDGES) atomicAdd(&g_deg[col[e]], 1);
}

__global__ void k_scan_dis() {
    __shared__ int sbuf[1024];
    __shared__ int s_carry;
    int t = threadIdx.x;
    if (t == 0) s_carry = 0;
    __syncthreads();
    for (int base = 0; base < N_NODES; base += 1024) {
        int idx = base + t;
        int v = (idx < N_NODES) ? g_deg[idx] : 0;
        sbuf[t] = v;
        __syncthreads();
        for (int off = 1; off < 1024; off <<= 1) {
            int y = (t >= off) ? sbuf[t - off] : 0;
            __syncthreads();
            sbuf[t] += y;
            __syncthreads();
        }
        int incl = sbuf[t];
        int carry = s_carry;
        if (idx < N_NODES) {
            int excl = carry + incl - v;
            g_indptr[idx] = excl;
            g_cursor[idx] = excl;
            g_dis[idx] = rsqrtf((float)(v + 1));
        }
        __syncthreads();
        if (t == 1023) s_carry = carry + sbuf[1023];
        __syncthreads();
    }
    if (t == 0) g_indptr[N_NODES] = s_carry;
}

__global__ void k_fill_csr(const int* __restrict__ row, const int* __restrict__ col) {
    int e = blockIdx.x * blockDim.x + threadIdx.x;
    if (e < N_EDGES) {
        int r = row[e], c = col[e];
        float nrm = g_dis[r] * g_dis[c];
        int pos = atomicAdd(&g_cursor[c], 1);
        g_csr_src[pos] = r;
        g_csr_nrm[pos] = nrm;
    }
}

// ---------------- W transpose + bf16 hi/lo split (once) ---------------------
__global__ void k_split_w(const float* __restrict__ convs_W,
                          const float* __restrict__ fc0_W) {
    int idx = blockIdx.x * 256 + threadIdx.x;
    if (idx >= 10 * 16384) return;
    int l = idx >> 14;
    int kk = (idx >> 7) & 127;
    int n = idx & 127;
    float v = (l < 8) ? convs_W[idx] : fc0_W[idx - 8 * 16384];
    __nv_bfloat16 hi = __float2bfloat16(v);
    float lo = v - __bfloat162float(hi);
    int dst = (l << 14) + (n << 7) + kk;
    g_Wth[dst] = hi;
    g_Wtl[dst] = __float2bfloat16(lo);
}

// ---------------- tensor-core node GEMM (bf16x2 3-pass, ~fp32 accurate) -----
// out[M,128] = Ain[M,128] @ W_l[128,128] (+bias). CTA: 64 rows, 256 thr/8 warps.
// Warp tile m16 x n64 (rblk = wid>>1, cblk = wid&1).
#define XS_STRIDE 136   // bf16 elements per row (272 B)
#define SGT_XH 0
#define SGT_XL 17408
#define SGT_WH 34816
#define SGT_WL 69632
#define SGT_BYTES 104448

__global__ void __launch_bounds__(256, 2) k_sgemm_tc(
    const float* __restrict__ Aext, int a_sel, int out_sel, int layer,
    const float* __restrict__ bias, int M) {
    extern __shared__ char smc[];
    const float* Ain = a_sel ? g_h : Aext;
    float* out = (out_sel == 0) ? g_hw : (out_sel == 1 ? g_A : g_B);

    int tid = threadIdx.x;
    int lane = tid & 31, wid = tid >> 5;
    int rowBase = blockIdx.x * 64;

    // --- stage X split (64 x 128 fp32 -> hi/lo bf16, stride 136) ------------
    {
        const float4* A4 = (const float4*)Ain;
        uint32_t* Xh32 = (uint32_t*)(smc + SGT_XH);
        uint32_t* Xl32 = (uint32_t*)(smc + SGT_XL);
#pragma unroll
        for (int i = 0; i < 8; i++) {
            int idx = tid + i * 256;            // 2048 float4
            int rr = idx >> 5, c4 = idx & 31;
            float4 v = make_float4(0.f, 0.f, 0.f, 0.f);
            if (rowBase + rr < M) v = A4[(rowBase + rr) * 32 + c4];
            __nv_bfloat16 h0 = __float2bfloat16(v.x);
            __nv_bfloat16 h1 = __float2bfloat16(v.y);
            __nv_bfloat16 h2 = __float2bfloat16(v.z);
            __nv_bfloat16 h3 = __float2bfloat16(v.w);
            uint32_t hp0 = (uint32_t)__bfloat16_as_ushort(h0) |
                           ((uint32_t)__bfloat16_as_ushort(h1) << 16);
            uint32_t hp1 = (uint32_t)__bfloat16_as_ushort(h2) |
                           ((uint32_t)__bfloat16_as_ushort(h3) << 16);
            uint32_t lp0 = pack_bf16(v.x - __bfloat162float(h0), v.y - __bfloat162float(h1));
            uint32_t lp1 = pack_bf16(v.z - __bfloat162float(h2), v.w - __bfloat162float(h3));
            int o = rr * 68 + c4 * 2;
            *(uint2*)&Xh32[o] = make_uint2(hp0, hp1);
            *(uint2*)&Xl32[o] = make_uint2(lp0, lp1);
        }
    }
    // --- stage W hi/lo (pre-transposed [n][k]) -------------------------------
    {
        const uint4* Wh4 = (const uint4*)(g_Wth + layer * 16384);
        const uint4* Wl4 = (const uint4*)(g_Wtl + layer * 16384);
#pragma unroll
        for (int i = 0; i < 8; i++) {
            int idx = tid + i * 256;            // 2048 uint4 (8 bf16 each)
            int rr = idx >> 4, c8 = idx & 15;
            *(uint4*)(smc + SGT_WH + rr * 272 + c8 * 16) = Wh4[rr * 16 + c8];
            *(uint4*)(smc + SGT_WL + rr * 272 + c8 * 16) = Wl4[rr * 16 + c8];
        }
    }
    __syncthreads();

    int g = lane >> 2, tg = lane & 3;
    int rblk = wid >> 1, cblk = wid & 1;

    float acc[8][4];
#pragma unroll
    for (int n = 0; n < 8; n++)
#pragma unroll
        for (int j = 0; j < 4; j++) acc[n][j] = 0.f;

    uint32_t xh_sb = (uint32_t)__cvta_generic_to_shared(smc + SGT_XH);
    uint32_t xl_sb = (uint32_t)__cvta_generic_to_shared(smc + SGT_XL);
    uint32_t wh_sb = (uint32_t)__cvta_generic_to_shared(smc + SGT_WH);
    uint32_t wl_sb = (uint32_t)__cvta_generic_to_shared(smc + SGT_WL);

    int a_r = rblk * 16 + (lane & 7) + (lane & 8);
    int a_kel = (lane & 16) ? 8 : 0;            // element offset within k16
    uint32_t a_hi_base = xh_sb + (uint32_t)(a_r * 272 + a_kel * 2);
    uint32_t a_lo_base = xl_sb + (uint32_t)(a_r * 272 + a_kel * 2);
    int b_nloc = (lane & 7) + ((lane & 16) >> 1);
    int b_kel = (lane & 8);                     // 0 or 8 elements
    uint32_t b_rowoff = (uint32_t)((cblk * 64 + b_nloc) * 272 + b_kel * 2);

#pragma unroll
    for (int k = 0; k < 8; k++) {
        uint32_t ah[4], al[4];
        ldmx4(ah, a_hi_base + k * 32);
        ldmx4(al, a_lo_base + k * 32);
        uint32_t bh[4][4], bl[4][4];
#pragma unroll
        for (int nb2 = 0; nb2 < 4; nb2++) {
            uint32_t off = b_rowoff + (uint32_t)(nb2 * 16 * 272) + k * 32;
            ldmx4(bh[nb2], wh_sb + off);
            ldmx4(bl[nb2], wl_sb + off);
        }
#pragma unroll
        for (int nb = 0; nb < 8; nb++) {
            uint32_t b0h = bh[nb >> 1][(nb & 1) * 2], b1h = bh[nb >> 1][(nb & 1) * 2 + 1];
            uint32_t b0l = bl[nb >> 1][(nb & 1) * 2], b1l = bl[nb >> 1][(nb & 1) * 2 + 1];
            mma_bf16(acc[nb], ah, b0h, b1h);
            mma_bf16(acc[nb], al, b0h, b1h);
            mma_bf16(acc[nb], ah, b0l, b1l);
        }
    }

    // --- epilogue -------------------------------------------------------------
    int r0 = rowBase + rblk * 16 + g;
#pragma unroll
    for (int nb = 0; nb < 8; nb++) {
        int c = cblk * 64 + nb * 8 + 2 * tg;
        float bv0 = 0.f, bv1 = 0.f;
        if (bias) { bv0 = bias[c]; bv1 = bias[c + 1]; }
        if (r0 < M)
            *(float2*)&out[r0 * 128 + c] = make_float2(acc[nb][0] + bv0, acc[nb][1] + bv1);
        if (r0 + 8 < M)
            *(float2*)&out[(r0 + 8) * 128 + c] = make_float2(acc[nb][2] + bv0, acc[nb][3] + bv1);
    }
}

// ---------------- aggregation: h[n] = relu(self + sum + bias (+res)) --------
__global__ void k_agg(const float* __restrict__ bias, int residual) {
    int gw = (blockIdx.x * blockDim.x + threadIdx.x) >> 5;
    int lane = threadIdx.x & 31;
    if (gw >= N_NODES) return;
    int n = gw;

    const float4* hw4 = (const float4*)g_hw;
    float d = g_dis[n];
    float ds = d * d;
    float4 v = hw4[n * 32 + lane];
    float4 acc = make_float4(v.x * ds, v.y * ds, v.z * ds, v.w * ds);

    int e = g_indptr[n];
    int end = g_indptr[n + 1];
    for (; e + 4 <= end; e += 4) {
        int s0 = g_csr_src[e + 0], s1 = g_csr_src[e + 1];
        int s2 = g_csr_src[e + 2], s3 = g_csr_src[e + 3];
        float n0 = g_csr_nrm[e + 0], n1 = g_csr_nrm[e + 1];
        float n2 = g_csr_nrm[e + 2], n3 = g_csr_nrm[e + 3];
        float4 v0 = hw4[s0 * 32 + lane];
        float4 v1 = hw4[s1 * 32 + lane];
        float4 v2 = hw4[s2 * 32 + lane];
        float4 v3 = hw4[s3 * 32 + lane];
        acc.x += n0 * v0.x + n1 * v1.x + n2 * v2.x + n3 * v3.x;
        acc.y += n0 * v0.y + n1 * v1.y + n2 * v2.y + n3 * v3.y;
        acc.z += n0 * v0.z + n1 * v1.z + n2 * v2.z + n3 * v3.z;
        acc.w += n0 * v0.w + n1 * v1.w + n2 * v2.w + n3 * v3.w;
    }
    for (; e < end; e++) {
        int s = g_csr_src[e];
        float nr = g_csr_nrm[e];
        float4 vv = hw4[s * 32 + lane];
        acc.x += nr * vv.x; acc.y += nr * vv.y;
        acc.z += nr * vv.z; acc.w += nr * vv.w;
    }

    float4 b = ((const float4*)bias)[lane];
    acc = f4add(acc, b);
    if (residual) {
        float4 hp = ((const float4*)g_h)[n * 32 + lane];
        acc = f4add(acc, hp);
    }
    ((float4*)g_h)[n * 32 + lane] = f4relu(acc);
}

// ---------------- persistent fused edge MLP (mma.sync tf32) -----------------
// 296 CTAs loop over 64-edge tiles. 256 thr/8 warps, warp tile m32 x n32.
// W1/b1/w2 staged ONCE per CTA. out[e] = relu(relu(A[row]+B[col])@W1+b1).w2+b2
#define US_STRIDE 132
#define WS_STRIDE 136
#define SMEM_EDGE_FLOATS (64 * US_STRIDE + 128 * WS_STRIDE + 128 + 128 + 256)
#define N_TILES (N_EDGES / 64)
#define EDGE_GRID 296

__global__ void __launch_bounds__(256, 2) k_edge_mlp_mma(
    const int* __restrict__ row, const int* __restrict__ col,
    const float* __restrict__ W1, const float* __restrict__ b1,
    const float* __restrict__ w2, const float* __restrict__ b2,
    float* __restrict__ out) {
    extern __shared__ float sm[];
    float* Us   = sm;                         // 64 x 132
    float* Ws   = Us + 64 * US_STRIDE;        // 128 x 136 (tf32 bits)
    float* b1s  = Ws + 128 * WS_STRIDE;       // 128
    float* w2s  = b1s + 128;                  // 128
    float* pbuf = w2s + 128;                  // 4 x 64

    int tid = threadIdx.x;
    int lane = tid & 31, wid = tid >> 5;

    // --- stage W1 (tf32), b1, w2 ONCE ----------------------------------------
    uint32_t* Wsu = (uint32_t*)Ws;
#pragma unroll 4
    for (int it = 0; it < 64; it++) {
        int i = it * 256 + tid;
        int kk = i >> 7, n = i & 127;
        Wsu[kk * WS_STRIDE + n] = f2tf32(W1[i]);
    }
    if (tid < 128) { b1s[tid] = b1[tid]; w2s[tid] = w2[tid]; }
    float b2v = b2[0];
    __syncthreads();

    int rblk = wid >> 2, cblk = wid & 3;
    int g = lane >> 2, tg = lane & 3;
    const uint32_t* Usu = (const uint32_t*)Us;
    const float4* A4 = (const float4*)g_A;
    const float4* B4 = (const float4*)g_B;

    for (int tile = blockIdx.x; tile < N_TILES; tile += EDGE_GRID) {
        int e0 = tile * 64;

        // --- gather u = relu(A[row]+B[col]) -> Us (tf32); 4 thr/edge --------
        {
            int i = tid >> 2, h = tid & 3;
            int r = row[e0 + i] * 32, c = col[e0 + i] * 32;
            uint32_t* dst = (uint32_t*)(Us + i * US_STRIDE + h * 32);
#pragma unroll
            for (int q = 0; q < 8; q++) {
                float4 a = A4[r + h * 8 + q];
                float4 b = B4[c + h * 8 + q];
                dst[q * 4 + 0] = f2tf32(fmaxf(a.x + b.x, 0.f));
                dst[q * 4 + 1] = f2tf32(fmaxf(a.y + b.y, 0.f));
                dst[q * 4 + 2] = f2tf32(fmaxf(a.z + b.z, 0.f));
                dst[q * 4 + 3] = f2tf32(fmaxf(a.w + b.w, 0.f));
            }
        }
        __syncthreads();

        // --- mma mainloop ----------------------------------------------------
        float acc[2][4][4];
#pragma unroll
        for (int mt = 0; mt < 2; mt++)
#pragma unroll
            for (int n = 0; n < 4; n++)
#pragma unroll
                for (int j = 0; j < 4; j++) acc[mt][n][j] = 0.f;

#pragma unroll
        for (int k = 0; k < 16; k++) {
            int kc = k * 8 + tg;
            uint32_t a[2][4];
#pragma unroll
            for (int mt = 0; mt < 2; mt++) {
                const uint32_t* base = Usu + (rblk * 32 + mt * 16 + g) * US_STRIDE + kc;
                a[mt][0] = base[0];
                a[mt][1] = base[8 * US_STRIDE];
                a[mt][2] = base[4];
                a[mt][3] = base[8 * US_STRIDE + 4];
            }
            const uint32_t* brow0 = Wsu + kc * WS_STRIDE + cblk * 32 + g;
            const uint32_t* brow1 = brow0 + 4 * WS_STRIDE;
#pragma unroll
            for (int n = 0; n < 4; n++) {
                uint32_t bb0 = brow0[n * 8];
                uint32_t bb1 = brow1[n * 8];
                mma_tf32(acc[0][n], a[0], bb0, bb1);
                mma_tf32(acc[1][n], a[1], bb0, bb1);
            }
        }

        // --- epilogue: relu(+b1).w2, quad reduce, per-warp partials ----------
#pragma unroll
        for (int mt = 0; mt < 2; mt++) {
            float p0 = 0.f, p1 = 0.f;
#pragma unroll
            for (int n = 0; n < 4; n++) {
                int c0 = cblk * 32 + n * 8 + 2 * tg;
                float wv0 = w2s[c0], wv1 = w2s[c0 + 1];
                float bb0 = b1s[c0], bb1 = b1s[c0 + 1];
                p0 += fmaxf(acc[mt][n][0] + bb0, 0.f) * wv0 + fmaxf(acc[mt][n][1] + bb1, 0.f) * wv1;
                p1 += fmaxf(acc[mt][n][2] + bb0, 0.f) * wv0 + fmaxf(acc[mt][n][3] + bb1, 0.f) * wv1;
            }
            p0 += __shfl_xor_sync(0xffffffffu, p0, 1);
            p0 += __shfl_xor_sync(0xffffffffu, p0, 2);
            p1 += __shfl_xor_sync(0xffffffffu, p1, 1);
            p1 += __shfl_xor_sync(0xffffffffu, p1, 2);
            if (tg == 0) {
                int rr = rblk * 32 + mt * 16 + g;
                pbuf[cblk * 64 + rr] = p0;
                pbuf[cblk * 64 + rr + 8] = p1;
            }
        }
        __syncthreads();
        if (tid < 64)
            out[e0 + tid] = pbuf[tid] + pbuf[64 + tid] + pbuf[128 + tid] + pbuf[192 + tid] + b2v;
    }
}

// ---------------- launch -----------------------------------------------------
extern "C" void kernel_launch(void* const* d_in, const int* in_sizes, int n_in,
                              void* d_out, int out_size) {
    const float* x       = (const float*)d_in[0];
    const int*   ei      = (const int*)d_in[1];
    const float* convs_W = (const float*)d_in[2];
    const float* convs_b = (const float*)d_in[3];
    const float* fc0_W   = (const float*)d_in[4];
    const float* fc0_b   = (const float*)d_in[5];
    const float* fc1_W   = (const float*)d_in[6];
    const float* fc1_b   = (const float*)d_in[7];
    const float* fc2_W   = (const float*)d_in[8];
    const float* fc2_b   = (const float*)d_in[9];
    float* out = (float*)d_out;

    const int* row = ei;
    const int* col = ei + N_EDGES;

    const int SMEM_EDGE = SMEM_EDGE_FLOATS * 4;
    cudaFuncSetAttribute(k_sgemm_tc, cudaFuncAttributeMaxDynamicSharedMemorySize, SGT_BYTES);
    cudaFuncSetAttribute(k_edge_mlp_mma, cudaFuncAttributeMaxDynamicSharedMemorySize, SMEM_EDGE);

    // 1. degree / dis / CSR + weight splits
    k_zero_deg<<<(N_NODES + 255) / 256, 256>>>();
    k_count_deg<<<(N_EDGES + 255) / 256, 256>>>(col);
    k_scan_dis<<<1, 1024>>>();
    k_fill_csr<<<(N_EDGES + 255) / 256, 256>>>(row, col);
    k_split_w<<<(10 * 16384 + 255) / 256, 256>>>(convs_W, fc0_W);

    // 2. GCN layers (tensor-core GEMM + gather-sum aggregation)
    const int GRID_GEMM = (N_NODES + 63) / 64;
    for (int l = 0; l < N_LAYERS; l++) {
        k_sgemm_tc<<<GRID_GEMM, 256, SGT_BYTES>>>(x, (l == 0) ? 0 : 1, 0, l, nullptr, N_NODES);
        k_agg<<<(N_NODES * 32 + 255) / 256, 256>>>(convs_b + l * CDIM, (l == 0) ? 0 : 1);
    }

    // 3. factorized fc0: A = h@W0a + b0, B = h@W0b
    k_sgemm_tc<<<GRID_GEMM, 256, SGT_BYTES>>>(nullptr, 1, 1, 8, fc0_b, N_NODES);
    k_sgemm_tc<<<GRID_GEMM, 256, SGT_BYTES>>>(nullptr, 1, 2, 9, nullptr, N_NODES);

    // 4. persistent fused edge MLP
    k_edge_mlp_mma<<<EDGE_GRID, 256, SMEM_EDGE>>>(row, col, fc1_W, fc1_b,
                                                  fc2_W, fc2_b, out);
}

// round 6
// speedup vs baseline: 1.4003x; 1.4003x over previous
#include <cuda_runtime.h>
#include <cuda_bf16.h>
#include <cuda_fp16.h>
#include <cstdint>

#define N_NODES 50000
#define N_EDGES 1600000
#define CDIM 128
#define N_LAYERS 8

// ---------------- scratch (device globals; no allocation allowed) ----------
__device__ float g_h [N_NODES * CDIM];
__device__ float g_hw[N_NODES * CDIM];
__device__ float g_A [N_NODES * CDIM];
__device__ float g_B [N_NODES * CDIM];
__device__ float g_dis[N_NODES];
__device__ int   g_deg[N_NODES];
__device__ int   g_indptr[N_NODES + 1];
__device__ int   g_cursor[N_NODES];
__device__ int   g_csr_src[N_EDGES];
__device__ float g_csr_nrm[N_EDGES];
// transposed + hi/lo-split weights for node GEMMs: [10][n=128][k=128]
__device__ __nv_bfloat16 g_Wth[10 * 128 * 128];
__device__ __nv_bfloat16 g_Wtl[10 * 128 * 128];

// ---------------- helpers ----------------------------------------------------
__device__ __forceinline__ void mma_bf16(float d[4], const uint32_t a[4],
                                         uint32_t b0, uint32_t b1) {
    asm volatile(
        "mma.sync.aligned.m16n8k16.row.col.f32.bf16.bf16.f32 "
        "{%0,%1,%2,%3}, {%4,%5,%6,%7}, {%8,%9}, {%0,%1,%2,%3};"
        : "+f"(d[0]), "+f"(d[1]), "+f"(d[2]), "+f"(d[3])
        : "r"(a[0]), "r"(a[1]), "r"(a[2]), "r"(a[3]), "r"(b0), "r"(b1));
}
__device__ __forceinline__ void mma_fp16(float d[4], const uint32_t a[4],
                                         uint32_t b0, uint32_t b1) {
    asm volatile(
        "mma.sync.aligned.m16n8k16.row.col.f32.f16.f16.f32 "
        "{%0,%1,%2,%3}, {%4,%5,%6,%7}, {%8,%9}, {%0,%1,%2,%3};"
        : "+f"(d[0]), "+f"(d[1]), "+f"(d[2]), "+f"(d[3])
        : "r"(a[0]), "r"(a[1]), "r"(a[2]), "r"(a[3]), "r"(b0), "r"(b1));
}
__device__ __forceinline__ void ldmx4(uint32_t r[4], uint32_t addr) {
    asm volatile("ldmatrix.sync.aligned.m8n8.x4.shared.b16 {%0,%1,%2,%3}, [%4];"
                 : "=r"(r[0]), "=r"(r[1]), "=r"(r[2]), "=r"(r[3]) : "r"(addr));
}
__device__ __forceinline__ float4 f4add(float4 a, float4 b) {
    return make_float4(a.x + b.x, a.y + b.y, a.z + b.z, a.w + b.w);
}
__device__ __forceinline__ float4 f4relu(float4 a) {
    return make_float4(fmaxf(a.x, 0.f), fmaxf(a.y, 0.f), fmaxf(a.z, 0.f), fmaxf(a.w, 0.f));
}
__device__ __forceinline__ uint32_t pack_bf16(float a, float b) {
    uint32_t lo = (uint32_t)__bfloat16_as_ushort(__float2bfloat16(a));
    uint32_t hi = (uint32_t)__bfloat16_as_ushort(__float2bfloat16(b));
    return lo | (hi << 16);
}

// ---------------- setup kernels ---------------------------------------------
__global__ void k_zero_deg() {
    int i = blockIdx.x * blockDim.x + threadIdx.x;
    if (i < N_NODES) g_deg[i] = 0;
}

__global__ void k_count_deg(const int* __restrict__ col) {
    int e = blockIdx.x * blockDim.x + threadIdx.x;
    if (e < N_EDGES) atomicAdd(&g_deg[col[e]], 1);
}

__global__ void k_scan_dis() {
    __shared__ int sbuf[1024];
    __shared__ int s_carry;
    int t = threadIdx.x;
    if (t == 0) s_carry = 0;
    __syncthreads();
    for (int base = 0; base < N_NODES; base += 1024) {
        int idx = base + t;
        int v = (idx < N_NODES) ? g_deg[idx] : 0;
        sbuf[t] = v;
        __syncthreads();
        for (int off = 1; off < 1024; off <<= 1) {
            int y = (t >= off) ? sbuf[t - off] : 0;
            __syncthreads();
            sbuf[t] += y;
            __syncthreads();
        }
        int incl = sbuf[t];
        int carry = s_carry;
        if (idx < N_NODES) {
            int excl = carry + incl - v;
            g_indptr[idx] = excl;
            g_cursor[idx] = excl;
            g_dis[idx] = rsqrtf((float)(v + 1));
        }
        __syncthreads();
        if (t == 1023) s_carry = carry + sbuf[1023];
        __syncthreads();
    }
    if (t == 0) g_indptr[N_NODES] = s_carry;
}

__global__ void k_fill_csr(const int* __restrict__ row, const int* __restrict__ col) {
    int e = blockIdx.x * blockDim.x + threadIdx.x;
    if (e < N_EDGES) {
        int r = row[e], c = col[e];
        float nrm = g_dis[r] * g_dis[c];
        int pos = atomicAdd(&g_cursor[c], 1);
        g_csr_src[pos] = r;
        g_csr_nrm[pos] = nrm;
    }
}

// ---------------- W transpose + bf16 hi/lo split (once) ---------------------
__global__ void k_split_w(const float* __restrict__ convs_W,
                          const float* __restrict__ fc0_W) {
    int idx = blockIdx.x * 256 + threadIdx.x;
    if (idx >= 10 * 16384) return;
    int l = idx >> 14;
    int kk = (idx >> 7) & 127;
    int n = idx & 127;
    float v = (l < 8) ? convs_W[idx] : fc0_W[idx - 8 * 16384];
    __nv_bfloat16 hi = __float2bfloat16(v);
    float lo = v - __bfloat162float(hi);
    int dst = (l << 14) + (n << 7) + kk;
    g_Wth[dst] = hi;
    g_Wtl[dst] = __float2bfloat16(lo);
}

// ---------------- tensor-core node GEMM (bf16x2 3-pass, ~fp32 accurate) -----
// out[M,128] = Ain[M,128] @ W_l[128,128] (+bias). CTA: 64 rows, 256 thr/8 warps.
#define SGT_XH 0
#define SGT_XL 17408
#define SGT_WH 34816
#define SGT_WL 69632
#define SGT_BYTES 104448

__global__ void __launch_bounds__(256, 2) k_sgemm_tc(
    const float* __restrict__ Aext, int a_sel, int out_sel, int layer,
    const float* __restrict__ bias, int M) {
    extern __shared__ char smc[];
    const float* Ain = a_sel ? g_h : Aext;
    float* out = (out_sel == 0) ? g_hw : (out_sel == 1 ? g_A : g_B);

    int tid = threadIdx.x;
    int lane = tid & 31, wid = tid >> 5;
    int rowBase = blockIdx.x * 64;

    // --- stage X split (64 x 128 fp32 -> hi/lo bf16, stride 136) ------------
    {
        const float4* A4 = (const float4*)Ain;
        uint32_t* Xh32 = (uint32_t*)(smc + SGT_XH);
        uint32_t* Xl32 = (uint32_t*)(smc + SGT_XL);
#pragma unroll
        for (int i = 0; i < 8; i++) {
            int idx = tid + i * 256;
            int rr = idx >> 5, c4 = idx & 31;
            float4 v = make_float4(0.f, 0.f, 0.f, 0.f);
            if (rowBase + rr < M) v = A4[(rowBase + rr) * 32 + c4];
            __nv_bfloat16 h0 = __float2bfloat16(v.x);
            __nv_bfloat16 h1 = __float2bfloat16(v.y);
            __nv_bfloat16 h2 = __float2bfloat16(v.z);
            __nv_bfloat16 h3 = __float2bfloat16(v.w);
            uint32_t hp0 = (uint32_t)__bfloat16_as_ushort(h0) |
                           ((uint32_t)__bfloat16_as_ushort(h1) << 16);
            uint32_t hp1 = (uint32_t)__bfloat16_as_ushort(h2) |
                           ((uint32_t)__bfloat16_as_ushort(h3) << 16);
            uint32_t lp0 = pack_bf16(v.x - __bfloat162float(h0), v.y - __bfloat162float(h1));
            uint32_t lp1 = pack_bf16(v.z - __bfloat162float(h2), v.w - __bfloat162float(h3));
            int o = rr * 68 + c4 * 2;
            *(uint2*)&Xh32[o] = make_uint2(hp0, hp1);
            *(uint2*)&Xl32[o] = make_uint2(lp0, lp1);
        }
    }
    // --- stage W hi/lo (pre-transposed [n][k]) -------------------------------
    {
        const uint4* Wh4 = (const uint4*)(g_Wth + layer * 16384);
        const uint4* Wl4 = (const uint4*)(g_Wtl + layer * 16384);
#pragma unroll
        for (int i = 0; i < 8; i++) {
            int idx = tid + i * 256;
            int rr = idx >> 4, c8 = idx & 15;
            *(uint4*)(smc + SGT_WH + rr * 272 + c8 * 16) = Wh4[rr * 16 + c8];
            *(uint4*)(smc + SGT_WL + rr * 272 + c8 * 16) = Wl4[rr * 16 + c8];
        }
    }
    __syncthreads();

    int g = lane >> 2, tg = lane & 3;
    int rblk = wid >> 1, cblk = wid & 1;

    float acc[8][4];
#pragma unroll
    for (int n = 0; n < 8; n++)
#pragma unroll
        for (int j = 0; j < 4; j++) acc[n][j] = 0.f;

    uint32_t xh_sb = (uint32_t)__cvta_generic_to_shared(smc + SGT_XH);
    uint32_t xl_sb = (uint32_t)__cvta_generic_to_shared(smc + SGT_XL);
    uint32_t wh_sb = (uint32_t)__cvta_generic_to_shared(smc + SGT_WH);
    uint32_t wl_sb = (uint32_t)__cvta_generic_to_shared(smc + SGT_WL);

    int a_r = rblk * 16 + (lane & 7) + (lane & 8);
    int a_kel = (lane & 16) ? 8 : 0;
    uint32_t a_hi_base = xh_sb + (uint32_t)(a_r * 272 + a_kel * 2);
    uint32_t a_lo_base = xl_sb + (uint32_t)(a_r * 272 + a_kel * 2);
    int b_nloc = (lane & 7) + ((lane & 16) >> 1);
    int b_kel = (lane & 8);
    uint32_t b_rowoff = (uint32_t)((cblk * 64 + b_nloc) * 272 + b_kel * 2);

#pragma unroll
    for (int k = 0; k < 8; k++) {
        uint32_t ah[4], al[4];
        ldmx4(ah, a_hi_base + k * 32);
        ldmx4(al, a_lo_base + k * 32);
        uint32_t bh[4][4], bl[4][4];
#pragma unroll
        for (int nb2 = 0; nb2 < 4; nb2++) {
            uint32_t off = b_rowoff + (uint32_t)(nb2 * 16 * 272) + k * 32;
            ldmx4(bh[nb2], wh_sb + off);
            ldmx4(bl[nb2], wl_sb + off);
        }
#pragma unroll
        for (int nb = 0; nb < 8; nb++) {
            uint32_t b0h = bh[nb >> 1][(nb & 1) * 2], b1h = bh[nb >> 1][(nb & 1) * 2 + 1];
            uint32_t b0l = bl[nb >> 1][(nb & 1) * 2], b1l = bl[nb >> 1][(nb & 1) * 2 + 1];
            mma_bf16(acc[nb], ah, b0h, b1h);
            mma_bf16(acc[nb], al, b0h, b1h);
            mma_bf16(acc[nb], ah, b0l, b1l);
        }
    }

    // --- epilogue -------------------------------------------------------------
    int r0 = rowBase + rblk * 16 + g;
#pragma unroll
    for (int nb = 0; nb < 8; nb++) {
        int c = cblk * 64 + nb * 8 + 2 * tg;
        float bv0 = 0.f, bv1 = 0.f;
        if (bias) { bv0 = bias[c]; bv1 = bias[c + 1]; }
        if (r0 < M)
            *(float2*)&out[r0 * 128 + c] = make_float2(acc[nb][0] + bv0, acc[nb][1] + bv1);
        if (r0 + 8 < M)
            *(float2*)&out[(r0 + 8) * 128 + c] = make_float2(acc[nb][2] + bv0, acc[nb][3] + bv1);
    }
}

// ---------------- aggregation: h[n] = relu(self + sum + bias (+res)) --------
__global__ void k_agg(const float* __restrict__ bias, int residual) {
    int gw = (blockIdx.x * blockDim.x + threadIdx.x) >> 5;
    int lane = threadIdx.x & 31;
    if (gw >= N_NODES) return;
    int n = gw;

    const float4* hw4 = (const float4*)g_hw;
    float d = g_dis[n];
    float ds = d * d;
    float4 v = hw4[n * 32 + lane];
    float4 acc = make_float4(v.x * ds, v.y * ds, v.z * ds, v.w * ds);

    int e = g_indptr[n];
    int end = g_indptr[n + 1];
    for (; e + 4 <= end; e += 4) {
        int s0 = g_csr_src[e + 0], s1 = g_csr_src[e + 1];
        int s2 = g_csr_src[e + 2], s3 = g_csr_src[e + 3];
        float n0 = g_csr_nrm[e + 0], n1 = g_csr_nrm[e + 1];
        float n2 = g_csr_nrm[e + 2], n3 = g_csr_nrm[e + 3];
        float4 v0 = hw4[s0 * 32 + lane];
        float4 v1 = hw4[s1 * 32 + lane];
        float4 v2 = hw4[s2 * 32 + lane];
        float4 v3 = hw4[s3 * 32 + lane];
        acc.x += n0 * v0.x + n1 * v1.x + n2 * v2.x + n3 * v3.x;
        acc.y += n0 * v0.y + n1 * v1.y + n2 * v2.y + n3 * v3.y;
        acc.z += n0 * v0.z + n1 * v1.z + n2 * v2.z + n3 * v3.z;
        acc.w += n0 * v0.w + n1 * v1.w + n2 * v2.w + n3 * v3.w;
    }
    for (; e < end; e++) {
        int s = g_csr_src[e];
        float nr = g_csr_nrm[e];
        float4 vv = hw4[s * 32 + lane];
        acc.x += nr * vv.x; acc.y += nr * vv.y;
        acc.z += nr * vv.z; acc.w += nr * vv.w;
    }

    float4 b = ((const float4*)bias)[lane];
    acc = f4add(acc, b);
    if (residual) {
        float4 hp = ((const float4*)g_h)[n * 32 + lane];
        acc = f4add(acc, hp);
    }
    ((float4*)g_h)[n * 32 + lane] = f4relu(acc);
}

// ---------------- persistent fused edge MLP (mma.sync fp16, k16) ------------
// 296 CTAs loop over 128-edge tiles. 256 thr/8 warps, warp tile m32 x n64.
// W1 (fp16) staged ONCE. u = relu(A[row]+B[col]) computed fp32, rounded once
// to fp16. out[e] = relu(u @ W1 + b1) . w2 + b2, fp32 accumulation.
#define ESM_US 0                       // 128 x 136 fp16 = 34816 B
#define ESM_WS 34816                   // 128 x 136 fp16 = 34816 B
#define ESM_B1 69632                   // 128 f32
#define ESM_W2 70144                   // 128 f32
#define ESM_PB 70656                   // 2 x 128 f32
#define ESM_BYTES 71680
#define N_TILES (N_EDGES / 128)
#define EDGE_GRID 296

__global__ void __launch_bounds__(256, 2) k_edge_mlp_fp16(
    const int* __restrict__ row, const int* __restrict__ col,
    const float* __restrict__ W1, const float* __restrict__ b1,
    const float* __restrict__ w2, const float* __restrict__ b2,
    float* __restrict__ out) {
    extern __shared__ char smc[];
    __half* Ws  = (__half*)(smc + ESM_WS);
    float* b1s  = (float*)(smc + ESM_B1);
    float* w2s  = (float*)(smc + ESM_W2);
    float* pbuf = (float*)(smc + ESM_PB);

    int tid = threadIdx.x;
    int lane = tid & 31, wid = tid >> 5;

    // --- stage W1^T (fp16), b1, w2 ONCE --------------------------------------
#pragma unroll 4
    for (int it = 0; it < 64; it++) {
        int i = it * 256 + tid;
        int kk = i >> 7, n = i & 127;
        Ws[n * 136 + kk] = __float2half_rn(W1[i]);
    }
    if (tid < 128) { b1s[tid] = b1[tid]; w2s[tid] = w2[tid]; }
    float b2v = b2[0];
    __syncthreads();

    int rblk = wid >> 1, cblk = wid & 1;
    int g = lane >> 2, tg = lane & 3;

    uint32_t us_sb = (uint32_t)__cvta_generic_to_shared(smc + ESM_US);
    uint32_t ws_sb = (uint32_t)__cvta_generic_to_shared(smc + ESM_WS);
    // A-fragment base (per mt add mt*16 rows; per k-step add 32 B)
    uint32_t a_base = us_sb +
        (uint32_t)((rblk * 32 + (lane & 7) + (lane & 8)) * 272 + ((lane & 16) ? 16 : 0));
    // B-fragment base (W^T rows = n)
    uint32_t b_base = ws_sb +
        (uint32_t)((cblk * 64 + (lane & 7) + ((lane & 16) >> 1)) * 272 + (lane & 8) * 2);

    const float4* A4 = (const float4*)g_A;
    const float4* B4 = (const float4*)g_B;

    for (int tile = blockIdx.x; tile < N_TILES; tile += EDGE_GRID) {
        int e0 = tile * 128;

        // --- gather u = relu(A[row]+B[col]) -> Us (fp16); 2 thr/edge ---------
        // Each thread covers 64 channels: h=0 -> [0,64), h=1 -> [64,128).
        {
            int i = tid >> 1, h = tid & 1;
            int r = row[e0 + i] * 32, c = col[e0 + i] * 32;
            __half2* dst = (__half2*)(smc + ESM_US + i * 272 + h * 128);
#pragma unroll
            for (int q = 0; q < 16; q++) {
                float4 a = A4[r + h * 16 + q];
                float4 b = B4[c + h * 16 + q];
                dst[q * 2 + 0] = __floats2half2_rn(fmaxf(a.x + b.x, 0.f),
                                                   fmaxf(a.y + b.y, 0.f));
                dst[q * 2 + 1] = __floats2half2_rn(fmaxf(a.z + b.z, 0.f),
                                                   fmaxf(a.w + b.w, 0.f));
            }
        }
        __syncthreads();

        // --- fp16 mma mainloop (8 k16 steps) ---------------------------------
        float acc[2][8][4];
#pragma unroll
        for (int mt = 0; mt < 2; mt++)
#pragma unroll
            for (int n = 0; n < 8; n++)
#pragma unroll
                for (int j = 0; j < 4; j++) acc[mt][n][j] = 0.f;

#pragma unroll
        for (int k = 0; k < 8; k++) {
            uint32_t a0[4], a1[4];
            ldmx4(a0, a_base + k * 32);
            ldmx4(a1, a_base + 16 * 272 + k * 32);
            uint32_t bf[4][4];
#pragma unroll
            for (int nb2 = 0; nb2 < 4; nb2++)
                ldmx4(bf[nb2], b_base + (uint32_t)(nb2 * 16 * 272) + k * 32);
#pragma unroll
            for (int nb = 0; nb < 8; nb++) {
                uint32_t bb0 = bf[nb >> 1][(nb & 1) * 2];
                uint32_t bb1 = bf[nb >> 1][(nb & 1) * 2 + 1];
                mma_fp16(acc[0][nb], a0, bb0, bb1);
                mma_fp16(acc[1][nb], a1, bb0, bb1);
            }
        }

        // --- epilogue: relu(+b1).w2, quad reduce, cross-warp combine ---------
#pragma unroll
        for (int mt = 0; mt < 2; mt++) {
            float p0 = 0.f, p1 = 0.f;
#pragma unroll
            for (int nb = 0; nb < 8; nb++) {
                int c0 = cblk * 64 + nb * 8 + 2 * tg;
                float wv0 = w2s[c0], wv1 = w2s[c0 + 1];
                float bb0 = b1s[c0], bb1 = b1s[c0 + 1];
                p0 += fmaxf(acc[mt][nb][0] + bb0, 0.f) * wv0 + fmaxf(acc[mt][nb][1] + bb1, 0.f) * wv1;
                p1 += fmaxf(acc[mt][nb][2] + bb0, 0.f) * wv0 + fmaxf(acc[mt][nb][3] + bb1, 0.f) * wv1;
            }
            p0 += __shfl_xor_sync(0xffffffffu, p0, 1);
            p0 += __shfl_xor_sync(0xffffffffu, p0, 2);
            p1 += __shfl_xor_sync(0xffffffffu, p1, 1);
            p1 += __shfl_xor_sync(0xffffffffu, p1, 2);
            if (tg == 0) {
                int rr = rblk * 32 + mt * 16 + g;
                pbuf[cblk * 128 + rr] = p0;
                pbuf[cblk * 128 + rr + 8] = p1;
            }
        }
        __syncthreads();
        if (tid < 128) out[e0 + tid] = pbuf[tid] + pbuf[128 + tid] + b2v;
        __syncthreads();
    }
}

// ---------------- launch -----------------------------------------------------
extern "C" void kernel_launch(void* const* d_in, const int* in_sizes, int n_in,
                              void* d_out, int out_size) {
    const float* x       = (const float*)d_in[0];
    const int*   ei      = (const int*)d_in[1];
    const float* convs_W = (const float*)d_in[2];
    const float* convs_b = (const float*)d_in[3];
    const float* fc0_W   = (const float*)d_in[4];
    const float* fc0_b   = (const float*)d_in[5];
    const float* fc1_W   = (const float*)d_in[6];
    const float* fc1_b   = (const float*)d_in[7];
    const float* fc2_W   = (const float*)d_in[8];
    const float* fc2_b   = (const float*)d_in[9];
    float* out = (float*)d_out;

    const int* row = ei;
    const int* col = ei + N_EDGES;

    cudaFuncSetAttribute(k_sgemm_tc, cudaFuncAttributeMaxDynamicSharedMemorySize, SGT_BYTES);
    cudaFuncSetAttribute(k_edge_mlp_fp16, cudaFuncAttributeMaxDynamicSharedMemorySize, ESM_BYTES);

    // 1. degree / dis / CSR + weight splits
    k_zero_deg<<<(N_NODES + 255) / 256, 256>>>();
    k_count_deg<<<(N_EDGES + 255) / 256, 256>>>(col);
    k_scan_dis<<<1, 1024>>>();
    k_fill_csr<<<(N_EDGES + 255) / 256, 256>>>(row, col);
    k_split_w<<<(10 * 16384 + 255) / 256, 256>>>(convs_W, fc0_W);

    // 2. GCN layers (tensor-core GEMM + gather-sum aggregation)
    const int GRID_GEMM = (N_NODES + 63) / 64;
    for (int l = 0; l < N_LAYERS; l++) {
        k_sgemm_tc<<<GRID_GEMM, 256, SGT_BYTES>>>(x, (l == 0) ? 0 : 1, 0, l, nullptr, N_NODES);
        k_agg<<<(N_NODES * 32 + 255) / 256, 256>>>(convs_b + l * CDIM, (l == 0) ? 0 : 1);
    }

    // 3. factorized fc0: A = h@W0a + b0, B = h@W0b
    k_sgemm_tc<<<GRID_GEMM, 256, SGT_BYTES>>>(nullptr, 1, 1, 8, fc0_b, N_NODES);
    k_sgemm_tc<<<GRID_GEMM, 256, SGT_BYTES>>>(nullptr, 1, 2, 9, nullptr, N_NODES);

    // 4. persistent fused edge MLP (fp16 tensor cores)
    k_edge_mlp_fp16<<<EDGE_GRID, 256, ESM_BYTES>>>(row, col, fc1_W, fc1_b,
                                                   fc2_W, fc2_b, out);
}

// round 7
// speedup vs baseline: 1.4977x; 1.0695x over previous
#include <cuda_runtime.h>
#include <cuda_bf16.h>
#include <cuda_fp16.h>
#include <cstdint>

#define N_NODES 50000
#define N_EDGES 1600000
#define CDIM 128
#define N_LAYERS 8

// ---------------- scratch (device globals; no allocation allowed) ----------
__device__ float  g_h [N_NODES * CDIM];
__device__ __half g_hwh[N_NODES * CDIM];   // fp16 transformed features (gather table)
__device__ float  g_A [N_NODES * CDIM];
__device__ float  g_B [N_NODES * CDIM];
__device__ float  g_dis[N_NODES];
__device__ int    g_deg[N_NODES];
__device__ int    g_indptr[N_NODES + 1];
__device__ int    g_cursor[N_NODES];
__device__ int    g_csr_src[N_EDGES];
__device__ float  g_csr_nrm[N_EDGES];
// transposed + hi/lo-split weights for node GEMMs: [10][n=128][k=128]
__device__ __nv_bfloat16 g_Wth[10 * 128 * 128];
__device__ __nv_bfloat16 g_Wtl[10 * 128 * 128];

// ---------------- helpers ----------------------------------------------------
__device__ __forceinline__ void mma_bf16(float d[4], const uint32_t a[4],
                                         uint32_t b0, uint32_t b1) {
    asm volatile(
        "mma.sync.aligned.m16n8k16.row.col.f32.bf16.bf16.f32 "
        "{%0,%1,%2,%3}, {%4,%5,%6,%7}, {%8,%9}, {%0,%1,%2,%3};"
        : "+f"(d[0]), "+f"(d[1]), "+f"(d[2]), "+f"(d[3])
        : "r"(a[0]), "r"(a[1]), "r"(a[2]), "r"(a[3]), "r"(b0), "r"(b1));
}
__device__ __forceinline__ void mma_fp16(float d[4], const uint32_t a[4],
                                         uint32_t b0, uint32_t b1) {
    asm volatile(
        "mma.sync.aligned.m16n8k16.row.col.f32.f16.f16.f32 "
        "{%0,%1,%2,%3}, {%4,%5,%6,%7}, {%8,%9}, {%0,%1,%2,%3};"
        : "+f"(d[0]), "+f"(d[1]), "+f"(d[2]), "+f"(d[3])
        : "r"(a[0]), "r"(a[1]), "r"(a[2]), "r"(a[3]), "r"(b0), "r"(b1));
}
__device__ __forceinline__ void ldmx4(uint32_t r[4], uint32_t addr) {
    asm volatile("ldmatrix.sync.aligned.m8n8.x4.shared.b16 {%0,%1,%2,%3}, [%4];"
                 : "=r"(r[0]), "=r"(r[1]), "=r"(r[2]), "=r"(r[3]) : "r"(addr));
}
__device__ __forceinline__ float4 f4add(float4 a, float4 b) {
    return make_float4(a.x + b.x, a.y + b.y, a.z + b.z, a.w + b.w);
}
__device__ __forceinline__ float4 f4relu(float4 a) {
    return make_float4(fmaxf(a.x, 0.f), fmaxf(a.y, 0.f), fmaxf(a.z, 0.f), fmaxf(a.w, 0.f));
}
__device__ __forceinline__ uint32_t pack_bf16(float a, float b) {
    uint32_t lo = (uint32_t)__bfloat16_as_ushort(__float2bfloat16(a));
    uint32_t hi = (uint32_t)__bfloat16_as_ushort(__float2bfloat16(b));
    return lo | (hi << 16);
}
// accumulate 4 fp16 channels (uint2) scaled by nr into float4
__device__ __forceinline__ void acc_h4(float4& acc, uint2 raw, float nr) {
    __half2 h0 = *(__half2*)&raw.x;
    __half2 h1 = *(__half2*)&raw.y;
    float2 f0 = __half22float2(h0);
    float2 f1 = __half22float2(h1);
    acc.x += nr * f0.x; acc.y += nr * f0.y;
    acc.z += nr * f1.x; acc.w += nr * f1.y;
}

// ---------------- setup kernels ---------------------------------------------
__global__ void k_zero_deg() {
    int i = blockIdx.x * blockDim.x + threadIdx.x;
    if (i < N_NODES) g_deg[i] = 0;
}

__global__ void k_count_deg(const int* __restrict__ col) {
    int e = blockIdx.x * blockDim.x + threadIdx.x;
    if (e < N_EDGES) atomicAdd(&g_deg[col[e]], 1);
}

__global__ void k_scan_dis() {
    __shared__ int sbuf[1024];
    __shared__ int s_carry;
    int t = threadIdx.x;
    if (t == 0) s_carry = 0;
    __syncthreads();
    for (int base = 0; base < N_NODES; base += 1024) {
        int idx = base + t;
        int v = (idx < N_NODES) ? g_deg[idx] : 0;
        sbuf[t] = v;
        __syncthreads();
        for (int off = 1; off < 1024; off <<= 1) {
            int y = (t >= off) ? sbuf[t - off] : 0;
            __syncthreads();
            sbuf[t] += y;
            __syncthreads();
        }
        int incl = sbuf[t];
        int carry = s_carry;
        if (idx < N_NODES) {
            int excl = carry + incl - v;
            g_indptr[idx] = excl;
            g_cursor[idx] = excl;
            g_dis[idx] = rsqrtf((float)(v + 1));
        }
        __syncthreads();
        if (t == 1023) s_carry = carry + sbuf[1023];
        __syncthreads();
    }
    if (t == 0) g_indptr[N_NODES] = s_carry;
}

__global__ void k_fill_csr(const int* __restrict__ row, const int* __restrict__ col) {
    int e = blockIdx.x * blockDim.x + threadIdx.x;
    if (e < N_EDGES) {
        int r = row[e], c = col[e];
        float nrm = g_dis[r] * g_dis[c];
        int pos = atomicAdd(&g_cursor[c], 1);
        g_csr_src[pos] = r;
        g_csr_nrm[pos] = nrm;
    }
}

// ---------------- W transpose + bf16 hi/lo split (once) ---------------------
__global__ void k_split_w(const float* __restrict__ convs_W,
                          const float* __restrict__ fc0_W) {
    int idx = blockIdx.x * 256 + threadIdx.x;
    if (idx >= 10 * 16384) return;
    int l = idx >> 14;
    int kk = (idx >> 7) & 127;
    int n = idx & 127;
    float v = (l < 8) ? convs_W[idx] : fc0_W[idx - 8 * 16384];
    __nv_bfloat16 hi = __float2bfloat16(v);
    float lo = v - __bfloat162float(hi);
    int dst = (l << 14) + (n << 7) + kk;
    g_Wth[dst] = hi;
    g_Wtl[dst] = __float2bfloat16(lo);
}

// ---------------- tensor-core node GEMM (bf16x2 3-pass, ~fp32 accurate) -----
// out[M,128] = Ain[M,128] @ W_l[128,128] (+bias). CTA: 64 rows, 256 thr/8 warps.
// out_sel==0 writes fp16 g_hwh (aggregation gather table); 1/2 -> fp32 A/B.
#define SGT_XH 0
#define SGT_XL 17408
#define SGT_WH 34816
#define SGT_WL 69632
#define SGT_BYTES 104448

__global__ void __launch_bounds__(256, 2) k_sgemm_tc(
    const float* __restrict__ Aext, int a_sel, int out_sel, int layer,
    const float* __restrict__ bias, int M) {
    extern __shared__ char smc[];
    const float* Ain = a_sel ? g_h : Aext;

    int tid = threadIdx.x;
    int lane = tid & 31, wid = tid >> 5;
    int rowBase = blockIdx.x * 64;

    // --- stage X split (64 x 128 fp32 -> hi/lo bf16, stride 136) ------------
    {
        const float4* A4 = (const float4*)Ain;
        uint32_t* Xh32 = (uint32_t*)(smc + SGT_XH);
        uint32_t* Xl32 = (uint32_t*)(smc + SGT_XL);
#pragma unroll
        for (int i = 0; i < 8; i++) {
            int idx = tid + i * 256;
            int rr = idx >> 5, c4 = idx & 31;
            float4 v = make_float4(0.f, 0.f, 0.f, 0.f);
            if (rowBase + rr < M) v = A4[(rowBase + rr) * 32 + c4];
            __nv_bfloat16 h0 = __float2bfloat16(v.x);
            __nv_bfloat16 h1 = __float2bfloat16(v.y);
            __nv_bfloat16 h2 = __float2bfloat16(v.z);
            __nv_bfloat16 h3 = __float2bfloat16(v.w);
            uint32_t hp0 = (uint32_t)__bfloat16_as_ushort(h0) |
                           ((uint32_t)__bfloat16_as_ushort(h1) << 16);
            uint32_t hp1 = (uint32_t)__bfloat16_as_ushort(h2) |
                           ((uint32_t)__bfloat16_as_ushort(h3) << 16);
            uint32_t lp0 = pack_bf16(v.x - __bfloat162float(h0), v.y - __bfloat162float(h1));
            uint32_t lp1 = pack_bf16(v.z - __bfloat162float(h2), v.w - __bfloat162float(h3));
            int o = rr * 68 + c4 * 2;
            *(uint2*)&Xh32[o] = make_uint2(hp0, hp1);
            *(uint2*)&Xl32[o] = make_uint2(lp0, lp1);
        }
    }
    // --- stage W hi/lo (pre-transposed [n][k]) -------------------------------
    {
        const uint4* Wh4 = (const uint4*)(g_Wth + layer * 16384);
        const uint4* Wl4 = (const uint4*)(g_Wtl + layer * 16384);
#pragma unroll
        for (int i = 0; i < 8; i++) {
            int idx = tid + i * 256;
            int rr = idx >> 4, c8 = idx & 15;
            *(uint4*)(smc + SGT_WH + rr * 272 + c8 * 16) = Wh4[rr * 16 + c8];
            *(uint4*)(smc + SGT_WL + rr * 272 + c8 * 16) = Wl4[rr * 16 + c8];
        }
    }
    __syncthreads();

    int g = lane >> 2, tg = lane & 3;
    int rblk = wid >> 1, cblk = wid & 1;

    float acc[8][4];
#pragma unroll
    for (int n = 0; n < 8; n++)
#pragma unroll
        for (int j = 0; j < 4; j++) acc[n][j] = 0.f;

    uint32_t xh_sb = (uint32_t)__cvta_generic_to_shared(smc + SGT_XH);
    uint32_t xl_sb = (uint32_t)__cvta_generic_to_shared(smc + SGT_XL);
    uint32_t wh_sb = (uint32_t)__cvta_generic_to_shared(smc + SGT_WH);
    uint32_t wl_sb = (uint32_t)__cvta_generic_to_shared(smc + SGT_WL);

    int a_r = rblk * 16 + (lane & 7) + (lane & 8);
    int a_kel = (lane & 16) ? 8 : 0;
    uint32_t a_hi_base = xh_sb + (uint32_t)(a_r * 272 + a_kel * 2);
    uint32_t a_lo_base = xl_sb + (uint32_t)(a_r * 272 + a_kel * 2);
    int b_nloc = (lane & 7) + ((lane & 16) >> 1);
    int b_kel = (lane & 8);
    uint32_t b_rowoff = (uint32_t)((cblk * 64 + b_nloc) * 272 + b_kel * 2);

#pragma unroll
    for (int k = 0; k < 8; k++) {
        uint32_t ah[4], al[4];
        ldmx4(ah, a_hi_base + k * 32);
        ldmx4(al, a_lo_base + k * 32);
        uint32_t bh[4][4], bl[4][4];
#pragma unroll
        for (int nb2 = 0; nb2 < 4; nb2++) {
            uint32_t off = b_rowoff + (uint32_t)(nb2 * 16 * 272) + k * 32;
            ldmx4(bh[nb2], wh_sb + off);
            ldmx4(bl[nb2], wl_sb + off);
        }
#pragma unroll
        for (int nb = 0; nb < 8; nb++) {
            uint32_t b0h = bh[nb >> 1][(nb & 1) * 2], b1h = bh[nb >> 1][(nb & 1) * 2 + 1];
            uint32_t b0l = bl[nb >> 1][(nb & 1) * 2], b1l = bl[nb >> 1][(nb & 1) * 2 + 1];
            mma_bf16(acc[nb], ah, b0h, b1h);
            mma_bf16(acc[nb], al, b0h, b1h);
            mma_bf16(acc[nb], ah, b0l, b1l);
        }
    }

    // --- epilogue -------------------------------------------------------------
    int r0 = rowBase + rblk * 16 + g;
    if (out_sel == 0) {
        __half2* oh = (__half2*)g_hwh;
#pragma unroll
        for (int nb = 0; nb < 8; nb++) {
            int c = cblk * 64 + nb * 8 + 2 * tg;
            if (r0 < M)
                oh[(r0 * 128 + c) >> 1] = __floats2half2_rn(acc[nb][0], acc[nb][1]);
            if (r0 + 8 < M)
                oh[((r0 + 8) * 128 + c) >> 1] = __floats2half2_rn(acc[nb][2], acc[nb][3]);
        }
    } else {
        float* out = (out_sel == 1) ? g_A : g_B;
#pragma unroll
        for (int nb = 0; nb < 8; nb++) {
            int c = cblk * 64 + nb * 8 + 2 * tg;
            float bv0 = 0.f, bv1 = 0.f;
            if (bias) { bv0 = bias[c]; bv1 = bias[c + 1]; }
            if (r0 < M)
                *(float2*)&out[r0 * 128 + c] = make_float2(acc[nb][0] + bv0, acc[nb][1] + bv1);
            if (r0 + 8 < M)
                *(float2*)&out[(r0 + 8) * 128 + c] = make_float2(acc[nb][2] + bv0, acc[nb][3] + bv1);
        }
    }
}

// ---------------- aggregation: h[n] = relu(self + sum + bias (+res)) --------
// gather table is fp16 (g_hwh): 256B/edge instead of 512B. fp32 accumulation.
__global__ void k_agg(const float* __restrict__ bias, int residual) {
    int gw = (blockIdx.x * blockDim.x + threadIdx.x) >> 5;
    int lane = threadIdx.x & 31;
    if (gw >= N_NODES) return;
    int n = gw;

    const uint2* hw2 = (const uint2*)g_hwh;   // 4 fp16 channels per uint2
    float d = g_dis[n];
    float ds = d * d;
    float4 acc = make_float4(0.f, 0.f, 0.f, 0.f);
    acc_h4(acc, hw2[n * 32 + lane], ds);       // self term

    int e = g_indptr[n];
    int end = g_indptr[n + 1];
    for (; e + 4 <= end; e += 4) {
        int s0 = g_csr_src[e + 0], s1 = g_csr_src[e + 1];
        int s2 = g_csr_src[e + 2], s3 = g_csr_src[e + 3];
        float n0 = g_csr_nrm[e + 0], n1 = g_csr_nrm[e + 1];
        float n2 = g_csr_nrm[e + 2], n3 = g_csr_nrm[e + 3];
        uint2 v0 = hw2[s0 * 32 + lane];
        uint2 v1 = hw2[s1 * 32 + lane];
        uint2 v2 = hw2[s2 * 32 + lane];
        uint2 v3 = hw2[s3 * 32 + lane];
        acc_h4(acc, v0, n0);
        acc_h4(acc, v1, n1);
        acc_h4(acc, v2, n2);
        acc_h4(acc, v3, n3);
    }
    for (; e < end; e++) {
        int s = g_csr_src[e];
        float nr = g_csr_nrm[e];
        acc_h4(acc, hw2[s * 32 + lane], nr);
    }

    float4 b = ((const float4*)bias)[lane];
    acc = f4add(acc, b);
    if (residual) {
        float4 hp = ((const float4*)g_h)[n * 32 + lane];
        acc = f4add(acc, hp);
    }
    ((float4*)g_h)[n * 32 + lane] = f4relu(acc);
}

// ---------------- persistent fused edge MLP (mma.sync fp16, k16) ------------
// 296 CTAs loop over 128-edge tiles. 256 thr/8 warps, warp tile m32 x n64.
#define ESM_US 0                       // 128 x 136 fp16 = 34816 B
#define ESM_WS 34816                   // 128 x 136 fp16 = 34816 B
#define ESM_B1 69632                   // 128 f32
#define ESM_W2 70144                   // 128 f32
#define ESM_PB 70656                   // 2 x 128 f32
#define ESM_BYTES 71680
#define N_TILES (N_EDGES / 128)
#define EDGE_GRID 296

__global__ void __launch_bounds__(256, 2) k_edge_mlp_fp16(
    const int* __restrict__ row, const int* __restrict__ col,
    const float* __restrict__ W1, const float* __restrict__ b1,
    const float* __restrict__ w2, const float* __restrict__ b2,
    float* __restrict__ out) {
    extern __shared__ char smc[];
    __half* Ws  = (__half*)(smc + ESM_WS);
    float* b1s  = (float*)(smc + ESM_B1);
    float* w2s  = (float*)(smc + ESM_W2);
    float* pbuf = (float*)(smc + ESM_PB);

    int tid = threadIdx.x;
    int lane = tid & 31, wid = tid >> 5;

    // --- stage W1^T (fp16), b1, w2 ONCE --------------------------------------
#pragma unroll 4
    for (int it = 0; it < 64; it++) {
        int i = it * 256 + tid;
        int kk = i >> 7, n = i & 127;
        Ws[n * 136 + kk] = __float2half_rn(W1[i]);
    }
    if (tid < 128) { b1s[tid] = b1[tid]; w2s[tid] = w2[tid]; }
    float b2v = b2[0];
    __syncthreads();

    int rblk = wid >> 1, cblk = wid & 1;
    int g = lane >> 2, tg = lane & 3;

    uint32_t us_sb = (uint32_t)__cvta_generic_to_shared(smc + ESM_US);
    uint32_t ws_sb = (uint32_t)__cvta_generic_to_shared(smc + ESM_WS);
    uint32_t a_base = us_sb +
        (uint32_t)((rblk * 32 + (lane & 7) + (lane & 8)) * 272 + ((lane & 16) ? 16 : 0));
    uint32_t b_base = ws_sb +
        (uint32_t)((cblk * 64 + (lane & 7) + ((lane & 16) >> 1)) * 272 + (lane & 8) * 2);

    const float4* A4 = (const float4*)g_A;
    const float4* B4 = (const float4*)g_B;

    for (int tile = blockIdx.x; tile < N_TILES; tile += EDGE_GRID) {
        int e0 = tile * 128;

        // --- gather u = relu(A[row]+B[col]) -> Us (fp16); 2 thr/edge ---------
        {
            int i = tid >> 1, h = tid & 1;
            int r = row[e0 + i] * 32, c = col[e0 + i] * 32;
            __half2* dst = (__half2*)(smc + ESM_US + i * 272 + h * 128);
#pragma unroll
            for (int q = 0; q < 16; q++) {
                float4 a = A4[r + h * 16 + q];
                float4 b = B4[c + h * 16 + q];
                dst[q * 2 + 0] = __floats2half2_rn(fmaxf(a.x + b.x, 0.f),
                                                   fmaxf(a.y + b.y, 0.f));
                dst[q * 2 + 1] = __floats2half2_rn(fmaxf(a.z + b.z, 0.f),
                                                   fmaxf(a.w + b.w, 0.f));
            }
        }
        __syncthreads();

        // --- fp16 mma mainloop (8 k16 steps) ---------------------------------
        float acc[2][8][4];
#pragma unroll
        for (int mt = 0; mt < 2; mt++)
#pragma unroll
            for (int n = 0; n < 8; n++)
#pragma unroll
                for (int j = 0; j < 4; j++) acc[mt][n][j] = 0.f;

#pragma unroll
        for (int k = 0; k < 8; k++) {
            uint32_t a0[4], a1[4];
            ldmx4(a0, a_base + k * 32);
            ldmx4(a1, a_base + 16 * 272 + k * 32);
            uint32_t bf[4][4];
#pragma unroll
            for (int nb2 = 0; nb2 < 4; nb2++)
                ldmx4(bf[nb2], b_base + (uint32_t)(nb2 * 16 * 272) + k * 32);
#pragma unroll
            for (int nb = 0; nb < 8; nb++) {
                uint32_t bb0 = bf[nb >> 1][(nb & 1) * 2];
                uint32_t bb1 = bf[nb >> 1][(nb & 1) * 2 + 1];
                mma_fp16(acc[0][nb], a0, bb0, bb1);
                mma_fp16(acc[1][nb], a1, bb0, bb1);
            }
        }

        // --- epilogue: relu(+b1).w2, quad reduce, cross-warp combine ---------
#pragma unroll
        for (int mt = 0; mt < 2; mt++) {
            float p0 = 0.f, p1 = 0.f;
#pragma unroll
            for (int nb = 0; nb < 8; nb++) {
                int c0 = cblk * 64 + nb * 8 + 2 * tg;
                float wv0 = w2s[c0], wv1 = w2s[c0 + 1];
                float bb0 = b1s[c0], bb1 = b1s[c0 + 1];
                p0 += fmaxf(acc[mt][nb][0] + bb0, 0.f) * wv0 + fmaxf(acc[mt][nb][1] + bb1, 0.f) * wv1;
                p1 += fmaxf(acc[mt][nb][2] + bb0, 0.f) * wv0 + fmaxf(acc[mt][nb][3] + bb1, 0.f) * wv1;
            }
            p0 += __shfl_xor_sync(0xffffffffu, p0, 1);
            p0 += __shfl_xor_sync(0xffffffffu, p0, 2);
            p1 += __shfl_xor_sync(0xffffffffu, p1, 1);
            p1 += __shfl_xor_sync(0xffffffffu, p1, 2);
            if (tg == 0) {
                int rr = rblk * 32 + mt * 16 + g;
                pbuf[cblk * 128 + rr] = p0;
                pbuf[cblk * 128 + rr + 8] = p1;
            }
        }
        __syncthreads();
        if (tid < 128) out[e0 + tid] = pbuf[tid] + pbuf[128 + tid] + b2v;
        __syncthreads();
    }
}

// ---------------- launch -----------------------------------------------------
extern "C" void kernel_launch(void* const* d_in, const int* in_sizes, int n_in,
                              void* d_out, int out_size) {
    const float* x       = (const float*)d_in[0];
    const int*   ei      = (const int*)d_in[1];
    const float* convs_W = (const float*)d_in[2];
    const float* convs_b = (const float*)d_in[3];
    const float* fc0_W   = (const float*)d_in[4];
    const float* fc0_b   = (const float*)d_in[5];
    const float* fc1_W   = (const float*)d_in[6];
    const float* fc1_b   = (const float*)d_in[7];
    const float* fc2_W   = (const float*)d_in[8];
    const float* fc2_b   = (const float*)d_in[9];
    float* out = (float*)d_out;

    const int* row = ei;
    const int* col = ei + N_EDGES;

    cudaFuncSetAttribute(k_sgemm_tc, cudaFuncAttributeMaxDynamicSharedMemorySize, SGT_BYTES);
    cudaFuncSetAttribute(k_edge_mlp_fp16, cudaFuncAttributeMaxDynamicSharedMemorySize, ESM_BYTES);

    // 1. degree / dis / CSR + weight splits
    k_zero_deg<<<(N_NODES + 255) / 256, 256>>>();
    k_count_deg<<<(N_EDGES + 255) / 256, 256>>>(col);
    k_scan_dis<<<1, 1024>>>();
    k_fill_csr<<<(N_EDGES + 255) / 256, 256>>>(row, col);
    k_split_w<<<(10 * 16384 + 255) / 256, 256>>>(convs_W, fc0_W);

    // 2. GCN layers (tensor-core GEMM + fp16 gather aggregation)
    const int GRID_GEMM = (N_NODES + 63) / 64;
    for (int l = 0; l < N_LAYERS; l++) {
        k_sgemm_tc<<<GRID_GEMM, 256, SGT_BYTES>>>(x, (l == 0) ? 0 : 1, 0, l, nullptr, N_NODES);
        k_agg<<<(N_NODES * 32 + 255) / 256, 256>>>(convs_b + l * CDIM, (l == 0) ? 0 : 1);
    }

    // 3. factorized fc0: A = h@W0a + b0, B = h@W0b
    k_sgemm_tc<<<GRID_GEMM, 256, SGT_BYTES>>>(nullptr, 1, 1, 8, fc0_b, N_NODES);
    k_sgemm_tc<<<GRID_GEMM, 256, SGT_BYTES>>>(nullptr, 1, 2, 9, nullptr, N_NODES);

    // 4. persistent fused edge MLP (fp16 tensor cores)
    k_edge_mlp_fp16<<<EDGE_GRID, 256, ESM_BYTES>>>(row, col, fc1_W, fc1_b,
                                                   fc2_W, fc2_b, out);
}

// round 8
// speedup vs baseline: 1.5194x; 1.0145x over previous
#include <cuda_runtime.h>
#include <cuda_bf16.h>
#include <cuda_fp16.h>
#include <cstdint>

#define N_NODES 50000
#define N_EDGES 1600000
#define CDIM 128
#define N_LAYERS 8

// ---------------- scratch (device globals; no allocation allowed) ----------
__device__ float  g_h [N_NODES * CDIM];
__device__ __half g_hwh[N_NODES * CDIM];   // fp16 transformed features (gather table)
__device__ float  g_A [N_NODES * CDIM];
__device__ float  g_B [N_NODES * CDIM];
__device__ float  g_dis[N_NODES];
__device__ int    g_deg[N_NODES];
__device__ int    g_indptr[N_NODES + 1];
__device__ int    g_cursor[N_NODES];
__device__ int    g_csr_src[N_EDGES];
__device__ float  g_csr_nrm[N_EDGES];
// transposed + hi/lo-split weights for node GEMMs: [10][n=128][k=128]
__device__ __nv_bfloat16 g_Wth[10 * 128 * 128];
__device__ __nv_bfloat16 g_Wtl[10 * 128 * 128];

// ---------------- helpers ----------------------------------------------------
__device__ __forceinline__ void mma_bf16(float d[4], const uint32_t a[4],
                                         uint32_t b0, uint32_t b1) {
    asm volatile(
        "mma.sync.aligned.m16n8k16.row.col.f32.bf16.bf16.f32 "
        "{%0,%1,%2,%3}, {%4,%5,%6,%7}, {%8,%9}, {%0,%1,%2,%3};"
        : "+f"(d[0]), "+f"(d[1]), "+f"(d[2]), "+f"(d[3])
        : "r"(a[0]), "r"(a[1]), "r"(a[2]), "r"(a[3]), "r"(b0), "r"(b1));
}
__device__ __forceinline__ void mma_fp16(float d[4], const uint32_t a[4],
                                         uint32_t b0, uint32_t b1) {
    asm volatile(
        "mma.sync.aligned.m16n8k16.row.col.f32.f16.f16.f32 "
        "{%0,%1,%2,%3}, {%4,%5,%6,%7}, {%8,%9}, {%0,%1,%2,%3};"
        : "+f"(d[0]), "+f"(d[1]), "+f"(d[2]), "+f"(d[3])
        : "r"(a[0]), "r"(a[1]), "r"(a[2]), "r"(a[3]), "r"(b0), "r"(b1));
}
__device__ __forceinline__ void ldmx4(uint32_t r[4], uint32_t addr) {
    asm volatile("ldmatrix.sync.aligned.m8n8.x4.shared.b16 {%0,%1,%2,%3}, [%4];"
                 : "=r"(r[0]), "=r"(r[1]), "=r"(r[2]), "=r"(r[3]) : "r"(addr));
}
__device__ __forceinline__ float4 f4add(float4 a, float4 b) {
    return make_float4(a.x + b.x, a.y + b.y, a.z + b.z, a.w + b.w);
}
__device__ __forceinline__ float4 f4relu(float4 a) {
    return make_float4(fmaxf(a.x, 0.f), fmaxf(a.y, 0.f), fmaxf(a.z, 0.f), fmaxf(a.w, 0.f));
}
__device__ __forceinline__ uint32_t pack_bf16(float a, float b) {
    uint32_t lo = (uint32_t)__bfloat16_as_ushort(__float2bfloat16(a));
    uint32_t hi = (uint32_t)__bfloat16_as_ushort(__float2bfloat16(b));
    return lo | (hi << 16);
}
// accumulate 4 fp16 channels (uint2) scaled by nr into float4
__device__ __forceinline__ void acc_h4(float4& acc, uint2 raw, float nr) {
    __half2 h0 = *(__half2*)&raw.x;
    __half2 h1 = *(__half2*)&raw.y;
    float2 f0 = __half22float2(h0);
    float2 f1 = __half22float2(h1);
    acc.x += nr * f0.x; acc.y += nr * f0.y;
    acc.z += nr * f1.x; acc.w += nr * f1.y;
}

// ---------------- setup kernels ---------------------------------------------
__global__ void k_zero_deg() {
    int i = blockIdx.x * blockDim.x + threadIdx.x;
    if (i < N_NODES) g_deg[i] = 0;
}

__global__ void k_count_deg(const int* __restrict__ col) {
    int e = blockIdx.x * blockDim.x + threadIdx.x;
    if (e < N_EDGES) atomicAdd(&g_deg[col[e]], 1);
}

__global__ void k_scan_dis() {
    __shared__ int sbuf[1024];
    __shared__ int s_carry;
    int t = threadIdx.x;
    if (t == 0) s_carry = 0;
    __syncthreads();
    for (int base = 0; base < N_NODES; base += 1024) {
        int idx = base + t;
        int v = (idx < N_NODES) ? g_deg[idx] : 0;
        sbuf[t] = v;
        __syncthreads();
        for (int off = 1; off < 1024; off <<= 1) {
            int y = (t >= off) ? sbuf[t - off] : 0;
            __syncthreads();
            sbuf[t] += y;
            __syncthreads();
        }
        int incl = sbuf[t];
        int carry = s_carry;
        if (idx < N_NODES) {
            int excl = carry + incl - v;
            g_indptr[idx] = excl;
            g_cursor[idx] = excl;
            g_dis[idx] = rsqrtf((float)(v + 1));
        }
        __syncthreads();
        if (t == 1023) s_carry = carry + sbuf[1023];
        __syncthreads();
    }
    if (t == 0) g_indptr[N_NODES] = s_carry;
}

__global__ void k_fill_csr(const int* __restrict__ row, const int* __restrict__ col) {
    int e = blockIdx.x * blockDim.x + threadIdx.x;
    if (e < N_EDGES) {
        int r = row[e], c = col[e];
        float nrm = g_dis[r] * g_dis[c];
        int pos = atomicAdd(&g_cursor[c], 1);
        g_csr_src[pos] = r;
        g_csr_nrm[pos] = nrm;
    }
}

// ---------------- W transpose + bf16 hi/lo split (once) ---------------------
__global__ void k_split_w(const float* __restrict__ convs_W,
                          const float* __restrict__ fc0_W) {
    int idx = blockIdx.x * 256 + threadIdx.x;
    if (idx >= 10 * 16384) return;
    int l = idx >> 14;
    int kk = (idx >> 7) & 127;
    int n = idx & 127;
    float v = (l < 8) ? convs_W[idx] : fc0_W[idx - 8 * 16384];
    __nv_bfloat16 hi = __float2bfloat16(v);
    float lo = v - __bfloat162float(hi);
    int dst = (l << 14) + (n << 7) + kk;
    g_Wth[dst] = hi;
    g_Wtl[dst] = __float2bfloat16(lo);
}

// ---------------- tensor-core node GEMM (bf16x2 3-pass, ~fp32 accurate) -----
// out[M,128] = Ain[M,128] @ W_l[128,128] (+bias). CTA: 64 rows, 256 thr/8 warps.
// out_sel==0 writes fp16 g_hwh (aggregation gather table); 1/2 -> fp32 A/B.
#define SGT_XH 0
#define SGT_XL 17408
#define SGT_WH 34816
#define SGT_WL 69632
#define SGT_BYTES 104448

__global__ void __launch_bounds__(256, 2) k_sgemm_tc(
    const float* __restrict__ Aext, int a_sel, int out_sel, int layer,
    const float* __restrict__ bias, int M) {
    extern __shared__ char smc[];
    const float* Ain = a_sel ? g_h : Aext;

    int tid = threadIdx.x;
    int lane = tid & 31, wid = tid >> 5;
    int rowBase = blockIdx.x * 64;

    // --- stage X split (64 x 128 fp32 -> hi/lo bf16, stride 136) ------------
    {
        const float4* A4 = (const float4*)Ain;
        uint32_t* Xh32 = (uint32_t*)(smc + SGT_XH);
        uint32_t* Xl32 = (uint32_t*)(smc + SGT_XL);
#pragma unroll
        for (int i = 0; i < 8; i++) {
            int idx = tid + i * 256;
            int rr = idx >> 5, c4 = idx & 31;
            float4 v = make_float4(0.f, 0.f, 0.f, 0.f);
            if (rowBase + rr < M) v = A4[(rowBase + rr) * 32 + c4];
            __nv_bfloat16 h0 = __float2bfloat16(v.x);
            __nv_bfloat16 h1 = __float2bfloat16(v.y);
            __nv_bfloat16 h2 = __float2bfloat16(v.z);
            __nv_bfloat16 h3 = __float2bfloat16(v.w);
            uint32_t hp0 = (uint32_t)__bfloat16_as_ushort(h0) |
                           ((uint32_t)__bfloat16_as_ushort(h1) << 16);
            uint32_t hp1 = (uint32_t)__bfloat16_as_ushort(h2) |
                           ((uint32_t)__bfloat16_as_ushort(h3) << 16);
            uint32_t lp0 = pack_bf16(v.x - __bfloat162float(h0), v.y - __bfloat162float(h1));
            uint32_t lp1 = pack_bf16(v.z - __bfloat162float(h2), v.w - __bfloat162float(h3));
            int o = rr * 68 + c4 * 2;
            *(uint2*)&Xh32[o] = make_uint2(hp0, hp1);
            *(uint2*)&Xl32[o] = make_uint2(lp0, lp1);
        }
    }
    // --- stage W hi/lo (pre-transposed [n][k]) -------------------------------
    {
        const uint4* Wh4 = (const uint4*)(g_Wth + layer * 16384);
        const uint4* Wl4 = (const uint4*)(g_Wtl + layer * 16384);
#pragma unroll
        for (int i = 0; i < 8; i++) {
            int idx = tid + i * 256;
            int rr = idx >> 4, c8 = idx & 15;
            *(uint4*)(smc + SGT_WH + rr * 272 + c8 * 16) = Wh4[rr * 16 + c8];
            *(uint4*)(smc + SGT_WL + rr * 272 + c8 * 16) = Wl4[rr * 16 + c8];
        }
    }
    __syncthreads();

    int g = lane >> 2, tg = lane & 3;
    int rblk = wid >> 1, cblk = wid & 1;

    float acc[8][4];
#pragma unroll
    for (int n = 0; n < 8; n++)
#pragma unroll
        for (int j = 0; j < 4; j++) acc[n][j] = 0.f;

    uint32_t xh_sb = (uint32_t)__cvta_generic_to_shared(smc + SGT_XH);
    uint32_t xl_sb = (uint32_t)__cvta_generic_to_shared(smc + SGT_XL);
    uint32_t wh_sb = (uint32_t)__cvta_generic_to_shared(smc + SGT_WH);
    uint32_t wl_sb = (uint32_t)__cvta_generic_to_shared(smc + SGT_WL);

    int a_r = rblk * 16 + (lane & 7) + (lane & 8);
    int a_kel = (lane & 16) ? 8 : 0;
    uint32_t a_hi_base = xh_sb + (uint32_t)(a_r * 272 + a_kel * 2);
    uint32_t a_lo_base = xl_sb + (uint32_t)(a_r * 272 + a_kel * 2);
    int b_nloc = (lane & 7) + ((lane & 16) >> 1);
    int b_kel = (lane & 8);
    uint32_t b_rowoff = (uint32_t)((cblk * 64 + b_nloc) * 272 + b_kel * 2);

#pragma unroll
    for (int k = 0; k < 8; k++) {
        uint32_t ah[4], al[4];
        ldmx4(ah, a_hi_base + k * 32);
        ldmx4(al, a_lo_base + k * 32);
        uint32_t bh[4][4], bl[4][4];
#pragma unroll
        for (int nb2 = 0; nb2 < 4; nb2++) {
            uint32_t off = b_rowoff + (uint32_t)(nb2 * 16 * 272) + k * 32;
            ldmx4(bh[nb2], wh_sb + off);
            ldmx4(bl[nb2], wl_sb + off);
        }
#pragma unroll
        for (int nb = 0; nb < 8; nb++) {
            uint32_t b0h = bh[nb >> 1][(nb & 1) * 2], b1h = bh[nb >> 1][(nb & 1) * 2 + 1];
            uint32_t b0l = bl[nb >> 1][(nb & 1) * 2], b1l = bl[nb >> 1][(nb & 1) * 2 + 1];
            mma_bf16(acc[nb], ah, b0h, b1h);
            mma_bf16(acc[nb], al, b0h, b1h);
            mma_bf16(acc[nb], ah, b0l, b1l);
        }
    }

    // --- epilogue -------------------------------------------------------------
    int r0 = rowBase + rblk * 16 + g;
    if (out_sel == 0) {
        __half2* oh = (__half2*)g_hwh;
#pragma unroll
        for (int nb = 0; nb < 8; nb++) {
            int c = cblk * 64 + nb * 8 + 2 * tg;
            if (r0 < M)
                oh[(r0 * 128 + c) >> 1] = __floats2half2_rn(acc[nb][0], acc[nb][1]);
            if (r0 + 8 < M)
                oh[((r0 + 8) * 128 + c) >> 1] = __floats2half2_rn(acc[nb][2], acc[nb][3]);
        }
    } else {
        float* out = (out_sel == 1) ? g_A : g_B;
#pragma unroll
        for (int nb = 0; nb < 8; nb++) {
            int c = cblk * 64 + nb * 8 + 2 * tg;
            float bv0 = 0.f, bv1 = 0.f;
            if (bias) { bv0 = bias[c]; bv1 = bias[c + 1]; }
            if (r0 < M)
                *(float2*)&out[r0 * 128 + c] = make_float2(acc[nb][0] + bv0, acc[nb][1] + bv1);
            if (r0 + 8 < M)
                *(float2*)&out[(r0 + 8) * 128 + c] = make_float2(acc[nb][2] + bv0, acc[nb][3] + bv1);
        }
    }
}

// ---------------- aggregation: h[n] = relu(self + sum + bias (+res)) --------
// fp16 gather table; 8-wide unrolled edge loop for deep MLP (8 gathers in flight).
__global__ void k_agg(const float* __restrict__ bias, int residual) {
    int gw = (blockIdx.x * blockDim.x + threadIdx.x) >> 5;
    int lane = threadIdx.x & 31;
    if (gw >= N_NODES) return;
    int n = gw;

    const uint2* hw2 = (const uint2*)g_hwh;   // 4 fp16 channels per uint2
    float d = g_dis[n];
    float ds = d * d;
    float4 acc = make_float4(0.f, 0.f, 0.f, 0.f);
    acc_h4(acc, hw2[n * 32 + lane], ds);       // self term

    int e = g_indptr[n];
    int end = g_indptr[n + 1];
    for (; e + 8 <= end; e += 8) {
        int s[8]; float nr[8]; uint2 v[8];
#pragma unroll
        for (int j = 0; j < 8; j++) { s[j] = g_csr_src[e + j]; nr[j] = g_csr_nrm[e + j]; }
#pragma unroll
        for (int j = 0; j < 8; j++) v[j] = hw2[s[j] * 32 + lane];
#pragma unroll
        for (int j = 0; j < 8; j++) acc_h4(acc, v[j], nr[j]);
    }
    if (e + 4 <= end) {
        int s[4]; float nr[4]; uint2 v[4];
#pragma unroll
        for (int j = 0; j < 4; j++) { s[j] = g_csr_src[e + j]; nr[j] = g_csr_nrm[e + j]; }
#pragma unroll
        for (int j = 0; j < 4; j++) v[j] = hw2[s[j] * 32 + lane];
#pragma unroll
        for (int j = 0; j < 4; j++) acc_h4(acc, v[j], nr[j]);
        e += 4;
    }
    for (; e < end; e++) {
        int s = g_csr_src[e];
        float nr = g_csr_nrm[e];
        acc_h4(acc, hw2[s * 32 + lane], nr);
    }

    float4 b = ((const float4*)bias)[lane];
    acc = f4add(acc, b);
    if (residual) {
        float4 hp = ((const float4*)g_h)[n * 32 + lane];
        acc = f4add(acc, hp);
    }
    ((float4*)g_h)[n * 32 + lane] = f4relu(acc);
}

// ---------------- persistent fused edge MLP (mma.sync fp16, k16) ------------
// 296 CTAs loop over 128-edge tiles. 256 thr/8 warps, warp tile m32 x n64.
#define ESM_US 0                       // 128 x 136 fp16 = 34816 B
#define ESM_WS 34816                   // 128 x 136 fp16 = 34816 B
#define ESM_B1 69632                   // 128 f32
#define ESM_W2 70144                   // 128 f32
#define ESM_PB 70656                   // 2 x 128 f32
#define ESM_BYTES 71680
#define N_TILES (N_EDGES / 128)
#define EDGE_GRID 296

__global__ void __launch_bounds__(256, 2) k_edge_mlp_fp16(
    const int* __restrict__ row, const int* __restrict__ col,
    const float* __restrict__ W1, const float* __restrict__ b1,
    const float* __restrict__ w2, const float* __restrict__ b2,
    float* __restrict__ out) {
    extern __shared__ char smc[];
    __half* Ws  = (__half*)(smc + ESM_WS);
    float* b1s  = (float*)(smc + ESM_B1);
    float* w2s  = (float*)(smc + ESM_W2);
    float* pbuf = (float*)(smc + ESM_PB);

    int tid = threadIdx.x;
    int lane = tid & 31, wid = tid >> 5;

    // --- stage W1^T (fp16), b1, w2 ONCE --------------------------------------
#pragma unroll 4
    for (int it = 0; it < 64; it++) {
        int i = it * 256 + tid;
        int kk = i >> 7, n = i & 127;
        Ws[n * 136 + kk] = __float2half_rn(W1[i]);
    }
    if (tid < 128) { b1s[tid] = b1[tid]; w2s[tid] = w2[tid]; }
    float b2v = b2[0];
    __syncthreads();

    int rblk = wid >> 1, cblk = wid & 1;
    int g = lane >> 2, tg = lane & 3;

    uint32_t us_sb = (uint32_t)__cvta_generic_to_shared(smc + ESM_US);
    uint32_t ws_sb = (uint32_t)__cvta_generic_to_shared(smc + ESM_WS);
    uint32_t a_base = us_sb +
        (uint32_t)((rblk * 32 + (lane & 7) + (lane & 8)) * 272 + ((lane & 16) ? 16 : 0));
    uint32_t b_base = ws_sb +
        (uint32_t)((cblk * 64 + (lane & 7) + ((lane & 16) >> 1)) * 272 + (lane & 8) * 2);

    const float4* A4 = (const float4*)g_A;
    const float4* B4 = (const float4*)g_B;

    for (int tile = blockIdx.x; tile < N_TILES; tile += EDGE_GRID) {
        int e0 = tile * 128;

        // --- gather u = relu(A[row]+B[col]) -> Us (fp16); 2 thr/edge ---------
        {
            int i = tid >> 1, h = tid & 1;
            int r = row[e0 + i] * 32, c = col[e0 + i] * 32;
            __half2* dst = (__half2*)(smc + ESM_US + i * 272 + h * 128);
#pragma unroll
            for (int q = 0; q < 16; q++) {
                float4 a = A4[r + h * 16 + q];
                float4 b = B4[c + h * 16 + q];
                dst[q * 2 + 0] = __floats2half2_rn(fmaxf(a.x + b.x, 0.f),
                                                   fmaxf(a.y + b.y, 0.f));
                dst[q * 2 + 1] = __floats2half2_rn(fmaxf(a.z + b.z, 0.f),
                                                   fmaxf(a.w + b.w, 0.f));
            }
        }
        __syncthreads();

        // --- fp16 mma mainloop (8 k16 steps) ---------------------------------
        float acc[2][8][4];
#pragma unroll
        for (int mt = 0; mt < 2; mt++)
#pragma unroll
            for (int n = 0; n < 8; n++)
#pragma unroll
                for (int j = 0; j < 4; j++) acc[mt][n][j] = 0.f;

#pragma unroll
        for (int k = 0; k < 8; k++) {
            uint32_t a0[4], a1[4];
            ldmx4(a0, a_base + k * 32);
            ldmx4(a1, a_base + 16 * 272 + k * 32);
            uint32_t bf[4][4];
#pragma unroll
            for (int nb2 = 0; nb2 < 4; nb2++)
                ldmx4(bf[nb2], b_base + (uint32_t)(nb2 * 16 * 272) + k * 32);
#pragma unroll
            for (int nb = 0; nb < 8; nb++) {
                uint32_t bb0 = bf[nb >> 1][(nb & 1) * 2];
                uint32_t bb1 = bf[nb >> 1][(nb & 1) * 2 + 1];
                mma_fp16(acc[0][nb], a0, bb0, bb1);
                mma_fp16(acc[1][nb], a1, bb0, bb1);
            }
        }

        // --- epilogue: relu(+b1).w2, quad reduce, cross-warp combine ---------
#pragma unroll
        for (int mt = 0; mt < 2; mt++) {
            float p0 = 0.f, p1 = 0.f;
#pragma unroll
            for (int nb = 0; nb < 8; nb++) {
                int c0 = cblk * 64 + nb * 8 + 2 * tg;
                float wv0 = w2s[c0], wv1 = w2s[c0 + 1];
                float bb0 = b1s[c0], bb1 = b1s[c0 + 1];
                p0 += fmaxf(acc[mt][nb][0] + bb0, 0.f) * wv0 + fmaxf(acc[mt][nb][1] + bb1, 0.f) * wv1;
                p1 += fmaxf(acc[mt][nb][2] + bb0, 0.f) * wv0 + fmaxf(acc[mt][nb][3] + bb1, 0.f) * wv1;
            }
            p0 += __shfl_xor_sync(0xffffffffu, p0, 1);
            p0 += __shfl_xor_sync(0xffffffffu, p0, 2);
            p1 += __shfl_xor_sync(0xffffffffu, p1, 1);
            p1 += __shfl_xor_sync(0xffffffffu, p1, 2);
            if (tg == 0) {
                int rr = rblk * 32 + mt * 16 + g;
                pbuf[cblk * 128 + rr] = p0;
                pbuf[cblk * 128 + rr + 8] = p1;
            }
        }
        __syncthreads();
        if (tid < 128) out[e0 + tid] = pbuf[tid] + pbuf[128 + tid] + b2v;
        __syncthreads();
    }
}

// ---------------- launch -----------------------------------------------------
extern "C" void kernel_launch(void* const* d_in, const int* in_sizes, int n_in,
                              void* d_out, int out_size) {
    const float* x       = (const float*)d_in[0];
    const int*   ei      = (const int*)d_in[1];
    const float* convs_W = (const float*)d_in[2];
    const float* convs_b = (const float*)d_in[3];
    const float* fc0_W   = (const float*)d_in[4];
    const float* fc0_b   = (const float*)d_in[5];
    const float* fc1_W   = (const float*)d_in[6];
    const float* fc1_b   = (const float*)d_in[7];
    const float* fc2_W   = (const float*)d_in[8];
    const float* fc2_b   = (const float*)d_in[9];
    float* out = (float*)d_out;

    const int* row = ei;
    const int* col = ei + N_EDGES;

    cudaFuncSetAttribute(k_sgemm_tc, cudaFuncAttributeMaxDynamicSharedMemorySize, SGT_BYTES);
    cudaFuncSetAttribute(k_edge_mlp_fp16, cudaFuncAttributeMaxDynamicSharedMemorySize, ESM_BYTES);

    const int GRID_GEMM = (N_NODES + 63) / 64;

    // 1. setup + layer-0 GEMM reordered so the ncu slot (4th launch) profiles
    //    k_sgemm_tc instead of k_fill_csr. Dependencies preserved:
    //    sgemm L0 needs only split_w; agg L0 needs fill_csr + sgemm L0.
    k_split_w<<<(10 * 16384 + 255) / 256, 256>>>(convs_W, fc0_W);
    k_zero_deg<<<(N_NODES + 255) / 256, 256>>>();
    k_count_deg<<<(N_EDGES + 255) / 256, 256>>>(col);
    k_sgemm_tc<<<GRID_GEMM, 256, SGT_BYTES>>>(x, 0, 0, 0, nullptr, N_NODES);   // L0 GEMM
    k_scan_dis<<<1, 1024>>>();
    k_fill_csr<<<(N_EDGES + 255) / 256, 256>>>(row, col);
    k_agg<<<(N_NODES * 32 + 255) / 256, 256>>>(convs_b, 0);                    // L0 agg

    // 2. GCN layers 1..7
    for (int l = 1; l < N_LAYERS; l++) {
        k_sgemm_tc<<<GRID_GEMM, 256, SGT_BYTES>>>(x, 1, 0, l, nullptr, N_NODES);
        k_agg<<<(N_NODES * 32 + 255) / 256, 256>>>(convs_b + l * CDIM, 1);
    }

    // 3. factorized fc0: A = h@W0a + b0, B = h@W0b
    k_sgemm_tc<<<GRID_GEMM, 256, SGT_BYTES>>>(nullptr, 1, 1, 8, fc0_b, N_NODES);
    k_sgemm_tc<<<GRID_GEMM, 256, SGT_BYTES>>>(nullptr, 1, 2, 9, nullptr, N_NODES);

    // 4. persistent fused edge MLP (fp16 tensor cores)
    k_edge_mlp_fp16<<<EDGE_GRID, 256, ESM_BYTES>>>(row, col, fc1_W, fc1_b,
                                                   fc2_W, fc2_b, out);
}